// round 16
// baseline (speedup 1.0000x reference)
#include <cuda_runtime.h>
#include <cuda_fp16.h>
#include <cstdint>
#include <math.h>

#define SEQ 1024
#define EMB 1024
#define BSZ 4
#define NH  16
#define HD  64
#define SCALING 0.125f
#define ATTN_CONST 3.032639477052158f
#define LOG2E 1.44269504088896340736f

// ---------------- fp16 scratch (device globals) -----------------------------
__device__ __half g_h16[BSZ * SEQ * EMB];
__device__ __half g_w16[4][EMB * EMB];
__device__ __half g_q16[BSZ * SEQ * EMB];
__device__ __half g_k16[BSZ * SEQ * EMB];
__device__ __half g_v16[BSZ * SEQ * EMB];
__device__ __half g_a16[BSZ * SEQ * EMB];

// ---------------- helpers ----------------------------------------------------
__device__ __forceinline__ uint32_t h2u(__half2 h) { return *(uint32_t*)&h; }
__device__ __forceinline__ uint32_t smem_u32(const void* p) {
    uint32_t a;
    asm("{ .reg .u64 t; cvta.to.shared.u64 t, %1; cvt.u32.u64 %0, t; }" : "=r"(a) : "l"(p));
    return a;
}
__device__ __forceinline__ void cp16(uint32_t dst, const void* src) {
    asm volatile("cp.async.ca.shared.global [%0], [%1], 16;" :: "r"(dst), "l"(src));
}
__device__ __forceinline__ void cp_commit() { asm volatile("cp.async.commit_group;" ::: "memory"); }
template <int N>
__device__ __forceinline__ void cp_wait() {
    asm volatile("cp.async.wait_group %0;" :: "n"(N) : "memory");
}
__device__ __forceinline__ void ldsm4(uint32_t* r, uint32_t addr) {
    asm volatile("ldmatrix.sync.aligned.m8n8.x4.shared.b16 {%0,%1,%2,%3}, [%4];"
                 : "=r"(r[0]), "=r"(r[1]), "=r"(r[2]), "=r"(r[3]) : "r"(addr));
}
__device__ __forceinline__ void ldsm4t(uint32_t* r, uint32_t addr) {
    asm volatile("ldmatrix.sync.aligned.m8n8.x4.trans.shared.b16 {%0,%1,%2,%3}, [%4];"
                 : "=r"(r[0]), "=r"(r[1]), "=r"(r[2]), "=r"(r[3]) : "r"(addr));
}
// Swizzle<3,3,3>: rows of 64 halves (128B), 8 chunks of 16B; byte offset in tile
__device__ __forceinline__ uint32_t swz(int r, int chunk) {
    return (uint32_t)(r * 128 + ((chunk ^ (r & 7)) << 4));
}
__device__ __forceinline__ void mma_f16(float* c, const uint32_t* a, const uint32_t* b) {
    asm volatile(
        "mma.sync.aligned.m16n8k16.row.col.f32.f16.f16.f32 "
        "{%0,%1,%2,%3}, {%4,%5,%6,%7}, {%8,%9}, {%0,%1,%2,%3};"
        : "+f"(c[0]), "+f"(c[1]), "+f"(c[2]), "+f"(c[3])
        : "r"(a[0]), "r"(a[1]), "r"(a[2]), "r"(a[3]), "r"(b[0]), "r"(b[1]));
}
// packed fp16x2 exp2 — one MUFU for two elements
__device__ __forceinline__ uint32_t h2ex2(uint32_t x) {
    uint32_t y;
    asm("ex2.approx.f16x2 %0, %1;" : "=r"(y) : "r"(x));
    return y;
}
__device__ __forceinline__ __half2 u2h(uint32_t x) { return *(__half2*)&x; }

// ---------------- fused f32 -> fp16 convert (all 5 tensors, 1 launch) --------
__global__ void __launch_bounds__(256)
conv_all(const float4* __restrict__ hid,
         const float4* __restrict__ wq, const float4* __restrict__ wk,
         const float4* __restrict__ wv, const float4* __restrict__ wo,
         uint2* __restrict__ h16d, uint2* __restrict__ w16d)
{
    int i = blockIdx.x * blockDim.x + threadIdx.x;   // 2097152 total
    float4 v;
    uint2* dst;
    if (i < 1048576) {
        v = hid[i];
        dst = h16d + i;
    } else {
        int j = i - 1048576;
        int w = j >> 18;
        int o = j & 262143;
        const float4* s = (w == 0) ? wq : (w == 1) ? wk : (w == 2) ? wv : wo;
        v = s[o];
        dst = w16d + j;
    }
    *dst = make_uint2(h2u(__floats2half2_rn(v.x, v.y)),
                      h2u(__floats2half2_rn(v.z, v.w)));
}

// ============ fp16 GEMM: C = (A @ W^T + b) * scale ==========================
// Round-14 best: BM=128, BN=256, BK=64, 256 threads, warp tile 64x64,
// 3-stage cp.async + ldmatrix + B-fragment double buffering.
template <bool OUT16>
__global__ void __launch_bounds__(256, 1)
hgemm(const __half* __restrict__ A,
      const __half* __restrict__ W0, const __half* __restrict__ W1,
      const __half* __restrict__ W2,
      const float* __restrict__ b0, const float* __restrict__ b1,
      const float* __restrict__ b2,
      void* __restrict__ C0, void* __restrict__ C1, void* __restrict__ C2,
      float scale0)
{
    extern __shared__ __align__(16) char smem[];
    const uint32_t sb = smem_u32(smem);

    const int z = blockIdx.z;
    const __half* W = (z == 0) ? W0 : (z == 1) ? W1 : W2;
    const float* bias = (z == 0) ? b0 : (z == 1) ? b1 : b2;
    void* C = (z == 0) ? C0 : (z == 1) ? C1 : C2;
    const float scale = (z == 0) ? scale0 : 1.0f;

    const int tid = threadIdx.x;
    const int wid = tid >> 5, lane = tid & 31;
    const int lq = lane >> 2, lr = lane & 3;
    const int lrow = lane & 15, lhi = lane >> 4, l8 = lane & 7, lg = (lane >> 3) & 1;
    const int warp_m = (wid & 1) * 64, warp_n = (wid >> 1) * 64;
    const int m0 = blockIdx.y * 128, n0 = blockIdx.x * 256;

    float acc[4][8][4];
#pragma unroll
    for (int mi = 0; mi < 4; mi++)
#pragma unroll
        for (int ni = 0; ni < 8; ni++)
#pragma unroll
            for (int j = 0; j < 4; j++) acc[mi][ni][j] = 0.f;

    auto issue = [&](int kk, int s) {
        const __half* Ag = A + (size_t)m0 * EMB + kk * 64;
        const __half* Wg = W + (size_t)n0 * EMB + kk * 64;
        uint32_t ab = sb + s * 16384u, bb = sb + 49152u + s * 32768u;
#pragma unroll
        for (int i = 0; i < 4; i++) {
            int q = tid + (i << 8);
            int r = q >> 3, c = q & 7;
            cp16(ab + swz(r, c), Ag + (size_t)r * EMB + c * 8);
        }
#pragma unroll
        for (int i = 0; i < 8; i++) {
            int q = tid + (i << 8);
            int r = q >> 3, c = q & 7;
            cp16(bb + swz(r, c), Wg + (size_t)r * EMB + c * 8);
        }
    };
    issue(0, 0); cp_commit();
    issue(1, 1); cp_commit();

    for (int kk = 0; kk < 16; kk++) {
        cp_wait<1>();
        __syncthreads();
        if (kk + 2 < 16) issue(kk + 2, (kk + 2) % 3);
        cp_commit();

        const int s = kk % 3;
        const uint32_t ab = sb + s * 16384u, bb = sb + 49152u + s * 32768u;

        uint32_t bfb[2][4][4];
#pragma unroll
        for (int np = 0; np < 4; np++)
            ldsm4(bfb[0][np], bb + swz(warp_n + (np * 2 + lhi) * 8 + l8, lg));

#pragma unroll
        for (int ks = 0; ks < 4; ks++) {
            uint32_t af[4][4];
#pragma unroll
            for (int mi = 0; mi < 4; mi++)
                ldsm4(af[mi], ab + swz(warp_m + mi * 16 + lrow, ks * 2 + lhi));
            if (ks < 3) {
#pragma unroll
                for (int np = 0; np < 4; np++)
                    ldsm4(bfb[(ks + 1) & 1][np],
                          bb + swz(warp_n + (np * 2 + lhi) * 8 + l8, (ks + 1) * 2 + lg));
            }
            const uint32_t (*bf)[4] = bfb[ks & 1];
#pragma unroll
            for (int mi = 0; mi < 4; mi++)
#pragma unroll
                for (int ni = 0; ni < 8; ni++)
                    mma_f16(acc[mi][ni], af[mi], &bf[ni >> 1][(ni & 1) * 2]);
        }
    }

#pragma unroll
    for (int mi = 0; mi < 4; mi++) {
#pragma unroll
        for (int ni = 0; ni < 8; ni++) {
            int row = m0 + warp_m + mi * 16 + lq;
            int col = n0 + warp_n + ni * 8 + (lr << 1);
            float2 bv = *(const float2*)(bias + col);
#pragma unroll
            for (int hh = 0; hh < 2; hh++) {
                int r = row + hh * 8;
                float x = (acc[mi][ni][hh * 2 + 0] + bv.x) * scale;
                float y = (acc[mi][ni][hh * 2 + 1] + bv.y) * scale;
                if (OUT16)
                    *(__half2*)((__half*)C + (size_t)r * EMB + col) = __floats2half2_rn(x, y);
                else
                    *(float2*)((float*)C + (size_t)r * EMB + col) = make_float2(x, y);
            }
        }
    }
}

// ================= fused flash attention, FM=64 / 128 thr / 2 CTAs per SM ===
// Same per-warp structure as the round-14 kernel (16 rows/warp, identical
// register footprint), but the CTA is halved so TWO CTAs co-reside per SM
// (smem 109.5KB each). Cross-CTA instruction streams fill each other's
// softmax/sync bubbles. Softmax: log2 domain, fixed ref -2, ex2.f16x2,
// HADD2 sums, epilogue-only SHFL reduce. K/V/bias: 3-stage cp.async.
#define BIAS_ROW 68   // floats per row (64 + 4 pad)
#define FM 64
__global__ void __launch_bounds__(128, 2)
flash16(const __half* __restrict__ Qg, const __half* __restrict__ Kg,
        const __half* __restrict__ Vg, const float* __restrict__ Bias,
        __half* __restrict__ Og)
{
    extern __shared__ __align__(16) char smem[];
    const uint32_t sb = smem_u32(smem);
    const uint32_t QBASE = sb;                   // 8192
    const uint32_t KBASE = sb + 8192u;           // 3 x 8192
    const uint32_t VBASE = sb + 32768u;          // 3 x 8192
    const uint32_t BBASE = sb + 57344u;          // 3 x 17408

    const int tid = threadIdx.x;
    const int wid = tid >> 5, lane = tid & 31;
    const int lq = lane >> 2, lr = lane & 3;
    const int lrow = lane & 15, lhi = lane >> 4, l8 = lane & 7, lg = (lane >> 3) & 1;
    const int wrow = wid * 16;
    const int m0 = blockIdx.x * FM;
    const int bh = blockIdx.y, b = bh >> 4, h = bh & 15;

    const __half* Qp = Qg + ((size_t)b * SEQ + m0) * EMB + h * HD;
    const __half* Kp = Kg + (size_t)b * SEQ * EMB + h * HD;
    const __half* Vp = Vg + (size_t)b * SEQ * EMB + h * HD;
    const float* Bp = Bias + ((size_t)bh * SEQ + m0) * SEQ;
    const float BC = ATTN_CONST * LOG2E;

    auto issueKVB = [&](int kb, int s) {
        const __half* Kr = Kp + (size_t)kb * 64 * EMB;
        const __half* Vr = Vp + (size_t)kb * 64 * EMB;
        uint32_t kb_ = KBASE + s * 8192u, vb_ = VBASE + s * 8192u;
#pragma unroll
        for (int i = 0; i < 4; i++) {
            int q = tid + (i << 7);
            int r = q >> 3, c = q & 7;
            cp16(kb_ + swz(r, c), Kr + (size_t)r * EMB + c * 8);
            cp16(vb_ + swz(r, c), Vr + (size_t)r * EMB + c * 8);
        }
        uint32_t bb_ = BBASE + s * 17408u;
        const float* Br = Bp + kb * 64;
#pragma unroll
        for (int i = 0; i < 8; i++) {
            int q = tid + (i << 7);
            int r = q >> 4, c = q & 15;
            cp16(bb_ + (uint32_t)(r * (BIAS_ROW * 4) + c * 16),
                 Br + (size_t)r * SEQ + c * 4);
        }
    };

    // Q tile (64x64) + stage 0/1 prefetch
#pragma unroll
    for (int i = 0; i < 4; i++) {
        int q = tid + (i << 7);
        int r = q >> 3, c = q & 7;
        cp16(QBASE + swz(r, c), Qp + (size_t)r * EMB + c * 8);
    }
    issueKVB(0, 0); cp_commit();
    issueKVB(1, 1); cp_commit();

    float oacc[8][4];
#pragma unroll
    for (int ni = 0; ni < 8; ni++)
#pragma unroll
        for (int j = 0; j < 4; j++) oacc[ni][j] = 0.f;
    float lac0 = 0.f, lac1 = 0.f;
    uint32_t qf[4][4];

    for (int kb = 0; kb < 16; kb++) {
        cp_wait<1>();
        __syncthreads();
        if (kb + 2 < 16) issueKVB(kb + 2, (kb + 2) % 3);
        cp_commit();

        if (kb == 0) {
#pragma unroll
            for (int ks = 0; ks < 4; ks++)
                ldsm4(qf[ks], QBASE + swz(wrow + lrow, ks * 2 + lhi));
        }

        const int s = kb % 3;
        const uint32_t kbase = KBASE + s * 8192u;
        const uint32_t vbase = VBASE + s * 8192u;
        const uint32_t bbase = BBASE + s * 17408u;

        // ---- bias smem -> regs EARLY (LDS latency hidden under QK mma) ----
        float2 br0[8], br1[8];
        {
            const uint32_t row0 = bbase + (uint32_t)(wrow + lq) * (BIAS_ROW * 4);
            const uint32_t row1 = row0 + 8u * (BIAS_ROW * 4);
#pragma unroll
            for (int ni = 0; ni < 8; ni++) {
                uint32_t co = (uint32_t)(ni * 8 + (lr << 1)) * 4u;
                br0[ni] = *(const float2*)(smem + (row0 + co - sb));
                br1[ni] = *(const float2*)(smem + (row1 + co - sb));
            }
        }

        // ---- S = Q @ K^T (log2 domain; acc pre-initialized to -2 = ref) ----
        float sacc[8][4];
#pragma unroll
        for (int ni = 0; ni < 8; ni++)
#pragma unroll
            for (int j = 0; j < 4; j++) sacc[ni][j] = -2.0f;
#pragma unroll
        for (int ks = 0; ks < 4; ks++) {
            uint32_t bf[4][4];
#pragma unroll
            for (int np = 0; np < 4; np++)
                ldsm4(bf[np], kbase + swz((np * 2 + lhi) * 8 + l8, ks * 2 + lg));
#pragma unroll
            for (int ni = 0; ni < 8; ni++)
                mma_f16(sacc[ni], qf[ks], &bf[ni >> 1][(ni & 1) * 2]);
        }

        // ---- P = 2^(S + BC*bias - 2) via packed f16x2 ex2 ----
        uint32_t pl[8], pu[8];
#pragma unroll
        for (int ni = 0; ni < 8; ni++) {
            float t0 = fmaf(BC, br0[ni].x, sacc[ni][0]);
            float t1 = fmaf(BC, br0[ni].y, sacc[ni][1]);
            float t2 = fmaf(BC, br1[ni].x, sacc[ni][2]);
            float t3 = fmaf(BC, br1[ni].y, sacc[ni][3]);
            pl[ni] = h2ex2(h2u(__floats2half2_rn(t0, t1)));
            pu[ni] = h2ex2(h2u(__floats2half2_rn(t2, t3)));
        }

        // ---- partial row sums via HADD2 tree (fp16, no overflow: <=13k) ----
        {
            __half2 a0 = __hadd2(__hadd2(u2h(pl[0]), u2h(pl[1])),
                                 __hadd2(u2h(pl[2]), u2h(pl[3])));
            __half2 a1 = __hadd2(__hadd2(u2h(pl[4]), u2h(pl[5])),
                                 __hadd2(u2h(pl[6]), u2h(pl[7])));
            float2 f0 = __half22float2(__hadd2(a0, a1));
            lac0 += f0.x + f0.y;
            __half2 b0_ = __hadd2(__hadd2(u2h(pu[0]), u2h(pu[1])),
                                  __hadd2(u2h(pu[2]), u2h(pu[3])));
            __half2 b1_ = __hadd2(__hadd2(u2h(pu[4]), u2h(pu[5])),
                                  __hadd2(u2h(pu[6]), u2h(pu[7])));
            float2 f1 = __half22float2(__hadd2(b0_, b1_));
            lac1 += f1.x + f1.y;
        }

        // ---- O += P @ V (V via ldmatrix.trans; P already fp16 A-frags) ----
#pragma unroll
        for (int ks = 0; ks < 4; ks++) {
            uint32_t a[4] = {pl[2 * ks], pu[2 * ks], pl[2 * ks + 1], pu[2 * ks + 1]};
            uint32_t bf[4][4];
#pragma unroll
            for (int np = 0; np < 4; np++)
                ldsm4t(bf[np], vbase + swz(ks * 16 + lg * 8 + l8, np * 2 + lhi));
#pragma unroll
            for (int ni = 0; ni < 8; ni++)
                mma_f16(oacc[ni], a, &bf[ni >> 1][(ni & 1) * 2]);
        }
    }

    // ---- epilogue: one-time row-sum reduce, normalize, fp16 store ----
    lac0 += __shfl_xor_sync(0xffffffffu, lac0, 1);
    lac0 += __shfl_xor_sync(0xffffffffu, lac0, 2);
    lac1 += __shfl_xor_sync(0xffffffffu, lac1, 1);
    lac1 += __shfl_xor_sync(0xffffffffu, lac1, 2);
    const float inv0 = 1.0f / lac0, inv1 = 1.0f / lac1;
    __half* Op0 = Og + ((size_t)b * SEQ + (m0 + wrow + lq)) * EMB + h * HD;
    __half* Op1 = Op0 + (size_t)8 * EMB;
#pragma unroll
    for (int ni = 0; ni < 8; ni++) {
        int c = ni * 8 + (lr << 1);
        *(__half2*)(Op0 + c) = __floats2half2_rn(oacc[ni][0] * inv0, oacc[ni][1] * inv0);
        *(__half2*)(Op1 + c) = __floats2half2_rn(oacc[ni][2] * inv1, oacc[ni][3] * inv1);
    }
}

// ---------------- launcher ---------------------------------------------------
extern "C" void kernel_launch(void* const* d_in, const int* in_sizes, int n_in,
                              void* d_out, int out_size)
{
    const float* hidden = (const float*)d_in[0];
    const float* attn_b = (const float*)d_in[1];
    const float* Wq = (const float*)d_in[2];
    const float* bq = (const float*)d_in[3];
    const float* Wk = (const float*)d_in[4];
    const float* bk = (const float*)d_in[5];
    const float* Wv = (const float*)d_in[6];
    const float* bv = (const float*)d_in[7];
    const float* Wo = (const float*)d_in[8];
    const float* bo = (const float*)d_in[9];
    float* out = (float*)d_out;

    __half *h16, *w16, *q16, *k16, *v16, *a16;
    cudaGetSymbolAddress((void**)&h16, g_h16);
    cudaGetSymbolAddress((void**)&w16, g_w16);
    cudaGetSymbolAddress((void**)&q16, g_q16);
    cudaGetSymbolAddress((void**)&k16, g_k16);
    cudaGetSymbolAddress((void**)&v16, g_v16);
    cudaGetSymbolAddress((void**)&a16, g_a16);

    const int GEMM_SMEM = 147456;                       // 3 x (16KB A + 32KB W)
    const int FLASH_SMEM = 8192 + 24576 + 24576 + 3 * 17408;   // 109568
    cudaFuncSetAttribute(hgemm<true>, cudaFuncAttributeMaxDynamicSharedMemorySize, GEMM_SMEM);
    cudaFuncSetAttribute(hgemm<false>, cudaFuncAttributeMaxDynamicSharedMemorySize, GEMM_SMEM);
    cudaFuncSetAttribute(flash16, cudaFuncAttributeMaxDynamicSharedMemorySize, FLASH_SMEM);

    // fused f32 -> fp16 conversions (single launch)
    conv_all<<<8192, 256>>>((const float4*)hidden, (const float4*)Wq,
                            (const float4*)Wk, (const float4*)Wv, (const float4*)Wo,
                            (uint2*)h16, (uint2*)w16);

    // QKV projections (fp16 out; q pre-scaled by SCALING*LOG2E for exp2 softmax)
    hgemm<true><<<dim3(EMB / 256, (BSZ * SEQ) / 128, 3), 256, GEMM_SMEM>>>(
        h16, w16, w16 + 1048576, w16 + 2 * 1048576,
        bq, bk, bv, q16, k16, v16, SCALING * LOG2E);

    // fused attention (FM=64, 128 threads, 2 CTAs/SM)
    flash16<<<dim3(SEQ / FM, BSZ * NH), 128, FLASH_SMEM>>>(q16, k16, v16, attn_b, a16);

    // output projection (f32 out)
    hgemm<false><<<dim3(EMB / 256, (BSZ * SEQ) / 128, 1), 256, GEMM_SMEM>>>(
        a16, w16 + 3 * 1048576, w16 + 3 * 1048576, w16 + 3 * 1048576,
        bo, bo, bo, out, out, out, 1.0f);
}

// round 17
// speedup vs baseline: 1.1372x; 1.1372x over previous
#include <cuda_runtime.h>
#include <cuda_fp16.h>
#include <cstdint>
#include <math.h>

#define SEQ 1024
#define EMB 1024
#define BSZ 4
#define NH  16
#define HD  64
#define SCALING 0.125f
#define ATTN_CONST 3.032639477052158f
#define LOG2E 1.44269504088896340736f

// ---------------- fp16 scratch (device globals) -----------------------------
__device__ __half g_h16[BSZ * SEQ * EMB];
__device__ __half g_w16[4][EMB * EMB];
__device__ __half g_q16[BSZ * SEQ * EMB];
__device__ __half g_k16[BSZ * SEQ * EMB];
__device__ __half g_v16[BSZ * SEQ * EMB];
__device__ __half g_a16[BSZ * SEQ * EMB];

// ---------------- helpers ----------------------------------------------------
__device__ __forceinline__ uint32_t h2u(__half2 h) { return *(uint32_t*)&h; }
__device__ __forceinline__ uint32_t smem_u32(const void* p) {
    uint32_t a;
    asm("{ .reg .u64 t; cvta.to.shared.u64 t, %1; cvt.u32.u64 %0, t; }" : "=r"(a) : "l"(p));
    return a;
}
// L2-only async copy: tiles are consumed once from smem, skip L1 allocation.
__device__ __forceinline__ void cp16(uint32_t dst, const void* src) {
    asm volatile("cp.async.cg.shared.global [%0], [%1], 16;" :: "r"(dst), "l"(src));
}
__device__ __forceinline__ void cp_commit() { asm volatile("cp.async.commit_group;" ::: "memory"); }
template <int N>
__device__ __forceinline__ void cp_wait() {
    asm volatile("cp.async.wait_group %0;" :: "n"(N) : "memory");
}
__device__ __forceinline__ void ldsm4(uint32_t* r, uint32_t addr) {
    asm volatile("ldmatrix.sync.aligned.m8n8.x4.shared.b16 {%0,%1,%2,%3}, [%4];"
                 : "=r"(r[0]), "=r"(r[1]), "=r"(r[2]), "=r"(r[3]) : "r"(addr));
}
__device__ __forceinline__ void ldsm4t(uint32_t* r, uint32_t addr) {
    asm volatile("ldmatrix.sync.aligned.m8n8.x4.trans.shared.b16 {%0,%1,%2,%3}, [%4];"
                 : "=r"(r[0]), "=r"(r[1]), "=r"(r[2]), "=r"(r[3]) : "r"(addr));
}
// Swizzle<3,3,3>: rows of 64 halves (128B), 8 chunks of 16B; byte offset in tile
__device__ __forceinline__ uint32_t swz(int r, int chunk) {
    return (uint32_t)(r * 128 + ((chunk ^ (r & 7)) << 4));
}
__device__ __forceinline__ void mma_f16(float* c, const uint32_t* a, const uint32_t* b) {
    asm volatile(
        "mma.sync.aligned.m16n8k16.row.col.f32.f16.f16.f32 "
        "{%0,%1,%2,%3}, {%4,%5,%6,%7}, {%8,%9}, {%0,%1,%2,%3};"
        : "+f"(c[0]), "+f"(c[1]), "+f"(c[2]), "+f"(c[3])
        : "r"(a[0]), "r"(a[1]), "r"(a[2]), "r"(a[3]), "r"(b[0]), "r"(b[1]));
}
// packed fp16x2 exp2 — one MUFU for two elements
__device__ __forceinline__ uint32_t h2ex2(uint32_t x) {
    uint32_t y;
    asm("ex2.approx.f16x2 %0, %1;" : "=r"(y) : "r"(x));
    return y;
}
__device__ __forceinline__ __half2 u2h(uint32_t x) { return *(__half2*)&x; }

// ---------------- fused f32 -> fp16 convert (all 5 tensors, 1 launch) --------
__global__ void __launch_bounds__(256)
conv_all(const float4* __restrict__ hid,
         const float4* __restrict__ wq, const float4* __restrict__ wk,
         const float4* __restrict__ wv, const float4* __restrict__ wo,
         uint2* __restrict__ h16d, uint2* __restrict__ w16d)
{
    int i = blockIdx.x * blockDim.x + threadIdx.x;   // 2097152 total
    float4 v;
    uint2* dst;
    if (i < 1048576) {
        v = hid[i];
        dst = h16d + i;
    } else {
        int j = i - 1048576;
        int w = j >> 18;
        int o = j & 262143;
        const float4* s = (w == 0) ? wq : (w == 1) ? wk : (w == 2) ? wv : wo;
        v = s[o];
        dst = w16d + j;
    }
    *dst = make_uint2(h2u(__floats2half2_rn(v.x, v.y)),
                      h2u(__floats2half2_rn(v.z, v.w)));
}

// ============ fp16 GEMM: C = (A @ W^T + b) * scale ==========================
// BM=128, BN=256, BK=64, 256 threads, warp tile 64x64, 3-stage cp.async,
// ldmatrix with BOTH A- and B-fragment double buffering across ks-steps.
template <bool OUT16>
__global__ void __launch_bounds__(256, 1)
hgemm(const __half* __restrict__ A,
      const __half* __restrict__ W0, const __half* __restrict__ W1,
      const __half* __restrict__ W2,
      const float* __restrict__ b0, const float* __restrict__ b1,
      const float* __restrict__ b2,
      void* __restrict__ C0, void* __restrict__ C1, void* __restrict__ C2,
      float scale0)
{
    extern __shared__ __align__(16) char smem[];
    const uint32_t sb = smem_u32(smem);

    const int z = blockIdx.z;
    const __half* W = (z == 0) ? W0 : (z == 1) ? W1 : W2;
    const float* bias = (z == 0) ? b0 : (z == 1) ? b1 : b2;
    void* C = (z == 0) ? C0 : (z == 1) ? C1 : C2;
    const float scale = (z == 0) ? scale0 : 1.0f;

    const int tid = threadIdx.x;
    const int wid = tid >> 5, lane = tid & 31;
    const int lq = lane >> 2, lr = lane & 3;
    const int lrow = lane & 15, lhi = lane >> 4, l8 = lane & 7, lg = (lane >> 3) & 1;
    const int warp_m = (wid & 1) * 64, warp_n = (wid >> 1) * 64;
    const int m0 = blockIdx.y * 128, n0 = blockIdx.x * 256;

    float acc[4][8][4];
#pragma unroll
    for (int mi = 0; mi < 4; mi++)
#pragma unroll
        for (int ni = 0; ni < 8; ni++)
#pragma unroll
            for (int j = 0; j < 4; j++) acc[mi][ni][j] = 0.f;

    auto issue = [&](int kk, int s) {
        const __half* Ag = A + (size_t)m0 * EMB + kk * 64;
        const __half* Wg = W + (size_t)n0 * EMB + kk * 64;
        uint32_t ab = sb + s * 16384u, bb = sb + 49152u + s * 32768u;
#pragma unroll
        for (int i = 0; i < 4; i++) {
            int q = tid + (i << 8);
            int r = q >> 3, c = q & 7;
            cp16(ab + swz(r, c), Ag + (size_t)r * EMB + c * 8);
        }
#pragma unroll
        for (int i = 0; i < 8; i++) {
            int q = tid + (i << 8);
            int r = q >> 3, c = q & 7;
            cp16(bb + swz(r, c), Wg + (size_t)r * EMB + c * 8);
        }
    };
    issue(0, 0); cp_commit();
    issue(1, 1); cp_commit();

    for (int kk = 0; kk < 16; kk++) {
        cp_wait<1>();
        __syncthreads();
        if (kk + 2 < 16) issue(kk + 2, (kk + 2) % 3);
        cp_commit();

        const int s = kk % 3;
        const uint32_t ab = sb + s * 16384u, bb = sb + 49152u + s * 32768u;

        // A/B fragment double buffers: preload ks=0
        uint32_t afb[2][4][4], bfb[2][4][4];
#pragma unroll
        for (int mi = 0; mi < 4; mi++)
            ldsm4(afb[0][mi], ab + swz(warp_m + mi * 16 + lrow, lhi));
#pragma unroll
        for (int np = 0; np < 4; np++)
            ldsm4(bfb[0][np], bb + swz(warp_n + (np * 2 + lhi) * 8 + l8, lg));

#pragma unroll
        for (int ks = 0; ks < 4; ks++) {
            if (ks < 3) {
#pragma unroll
                for (int mi = 0; mi < 4; mi++)
                    ldsm4(afb[(ks + 1) & 1][mi],
                          ab + swz(warp_m + mi * 16 + lrow, (ks + 1) * 2 + lhi));
#pragma unroll
                for (int np = 0; np < 4; np++)
                    ldsm4(bfb[(ks + 1) & 1][np],
                          bb + swz(warp_n + (np * 2 + lhi) * 8 + l8, (ks + 1) * 2 + lg));
            }
            const uint32_t (*af)[4] = afb[ks & 1];
            const uint32_t (*bf)[4] = bfb[ks & 1];
#pragma unroll
            for (int mi = 0; mi < 4; mi++)
#pragma unroll
                for (int ni = 0; ni < 8; ni++)
                    mma_f16(acc[mi][ni], af[mi], &bf[ni >> 1][(ni & 1) * 2]);
        }
    }

#pragma unroll
    for (int mi = 0; mi < 4; mi++) {
#pragma unroll
        for (int ni = 0; ni < 8; ni++) {
            int row = m0 + warp_m + mi * 16 + lq;
            int col = n0 + warp_n + ni * 8 + (lr << 1);
            float2 bv = *(const float2*)(bias + col);
#pragma unroll
            for (int hh = 0; hh < 2; hh++) {
                int r = row + hh * 8;
                float x = (acc[mi][ni][hh * 2 + 0] + bv.x) * scale;
                float y = (acc[mi][ni][hh * 2 + 1] + bv.y) * scale;
                if (OUT16)
                    *(__half2*)((__half*)C + (size_t)r * EMB + col) = __floats2half2_rn(x, y);
                else
                    *(float2*)((float*)C + (size_t)r * EMB + col) = make_float2(x, y);
            }
        }
    }
}

// ================= fused flash attention (round-14 config) ==================
// FM=128, 256 threads, 1 CTA/SM. fp16 mma, log2-domain scores, fixed ref -2,
// ex2.f16x2, HADD2 row sums, epilogue-only SHFL reduce.
// K/V/bias: 3-stage cp.async pipeline; bias smem->regs hoisted above QK mma.
#define BIAS_ROW 68   // floats per row (64 + 4 pad)
__global__ void __launch_bounds__(256, 1)
flash16(const __half* __restrict__ Qg, const __half* __restrict__ Kg,
        const __half* __restrict__ Vg, const float* __restrict__ Bias,
        __half* __restrict__ Og)
{
    extern __shared__ __align__(16) char smem[];
    const uint32_t sb = smem_u32(smem);
    const uint32_t KBASE = sb + 16384u;
    const uint32_t VBASE = sb + 40960u;
    const uint32_t BBASE = sb + 65536u;          // 3 stages x 34816 B

    const int tid = threadIdx.x;
    const int wid = tid >> 5, lane = tid & 31;
    const int lq = lane >> 2, lr = lane & 3;
    const int lrow = lane & 15, lhi = lane >> 4, l8 = lane & 7, lg = (lane >> 3) & 1;
    const int wrow = wid * 16;
    const int m0 = blockIdx.x * 128;
    const int bh = blockIdx.y, b = bh >> 4, h = bh & 15;

    const __half* Qp = Qg + ((size_t)b * SEQ + m0) * EMB + h * HD;
    const __half* Kp = Kg + (size_t)b * SEQ * EMB + h * HD;
    const __half* Vp = Vg + (size_t)b * SEQ * EMB + h * HD;
    const float* Bp = Bias + ((size_t)bh * SEQ + m0) * SEQ;
    const float BC = ATTN_CONST * LOG2E;

    auto issueKVB = [&](int kb, int s) {
        const __half* Kr = Kp + (size_t)kb * 64 * EMB;
        const __half* Vr = Vp + (size_t)kb * 64 * EMB;
        uint32_t kb_ = KBASE + s * 8192u, vb_ = VBASE + s * 8192u;
#pragma unroll
        for (int i = 0; i < 2; i++) {
            int q = tid + (i << 8);
            int r = q >> 3, c = q & 7;
            cp16(kb_ + swz(r, c), Kr + (size_t)r * EMB + c * 8);
            cp16(vb_ + swz(r, c), Vr + (size_t)r * EMB + c * 8);
        }
        uint32_t bb_ = BBASE + s * 34816u;
        const float* Br = Bp + kb * 64;
#pragma unroll
        for (int i = 0; i < 8; i++) {
            int q = tid + (i << 8);
            int r = q >> 4, c = q & 15;
            cp16(bb_ + (uint32_t)(r * (BIAS_ROW * 4) + c * 16),
                 Br + (size_t)r * SEQ + c * 4);
        }
    };

    // Q tile + stage 0/1 prefetch
#pragma unroll
    for (int i = 0; i < 4; i++) {
        int q = tid + (i << 8);
        int r = q >> 3, c = q & 7;
        cp16(sb + swz(r, c), Qp + (size_t)r * EMB + c * 8);
    }
    issueKVB(0, 0); cp_commit();
    issueKVB(1, 1); cp_commit();

    float oacc[8][4];
#pragma unroll
    for (int ni = 0; ni < 8; ni++)
#pragma unroll
        for (int j = 0; j < 4; j++) oacc[ni][j] = 0.f;
    float lac0 = 0.f, lac1 = 0.f;
    uint32_t qf[4][4];

    for (int kb = 0; kb < 16; kb++) {
        cp_wait<1>();
        __syncthreads();
        if (kb + 2 < 16) issueKVB(kb + 2, (kb + 2) % 3);
        cp_commit();

        if (kb == 0) {
#pragma unroll
            for (int ks = 0; ks < 4; ks++)
                ldsm4(qf[ks], sb + swz(wrow + lrow, ks * 2 + lhi));
        }

        const int s = kb % 3;
        const uint32_t kbase = KBASE + s * 8192u;
        const uint32_t vbase = VBASE + s * 8192u;
        const uint32_t bbase = BBASE + s * 34816u;

        // ---- bias smem -> regs EARLY (LDS latency hidden under QK mma) ----
        float2 br0[8], br1[8];
        {
            const uint32_t row0 = bbase + (uint32_t)(wrow + lq) * (BIAS_ROW * 4);
            const uint32_t row1 = row0 + 8u * (BIAS_ROW * 4);
#pragma unroll
            for (int ni = 0; ni < 8; ni++) {
                uint32_t co = (uint32_t)(ni * 8 + (lr << 1)) * 4u;
                br0[ni] = *(const float2*)(smem + (row0 + co - sb));
                br1[ni] = *(const float2*)(smem + (row1 + co - sb));
            }
        }

        // ---- S = Q @ K^T (log2 domain; acc pre-initialized to -2 = ref) ----
        float sacc[8][4];
#pragma unroll
        for (int ni = 0; ni < 8; ni++)
#pragma unroll
            for (int j = 0; j < 4; j++) sacc[ni][j] = -2.0f;
#pragma unroll
        for (int ks = 0; ks < 4; ks++) {
            uint32_t bf[4][4];
#pragma unroll
            for (int np = 0; np < 4; np++)
                ldsm4(bf[np], kbase + swz((np * 2 + lhi) * 8 + l8, ks * 2 + lg));
#pragma unroll
            for (int ni = 0; ni < 8; ni++)
                mma_f16(sacc[ni], qf[ks], &bf[ni >> 1][(ni & 1) * 2]);
        }

        // ---- P = 2^(S + BC*bias - 2) via packed f16x2 ex2 ----
        uint32_t pl[8], pu[8];
#pragma unroll
        for (int ni = 0; ni < 8; ni++) {
            float t0 = fmaf(BC, br0[ni].x, sacc[ni][0]);
            float t1 = fmaf(BC, br0[ni].y, sacc[ni][1]);
            float t2 = fmaf(BC, br1[ni].x, sacc[ni][2]);
            float t3 = fmaf(BC, br1[ni].y, sacc[ni][3]);
            pl[ni] = h2ex2(h2u(__floats2half2_rn(t0, t1)));
            pu[ni] = h2ex2(h2u(__floats2half2_rn(t2, t3)));
        }

        // ---- partial row sums via HADD2 tree (fp16, no overflow: <=13k) ----
        {
            __half2 a0 = __hadd2(__hadd2(u2h(pl[0]), u2h(pl[1])),
                                 __hadd2(u2h(pl[2]), u2h(pl[3])));
            __half2 a1 = __hadd2(__hadd2(u2h(pl[4]), u2h(pl[5])),
                                 __hadd2(u2h(pl[6]), u2h(pl[7])));
            float2 f0 = __half22float2(__hadd2(a0, a1));
            lac0 += f0.x + f0.y;
            __half2 b0_ = __hadd2(__hadd2(u2h(pu[0]), u2h(pu[1])),
                                  __hadd2(u2h(pu[2]), u2h(pu[3])));
            __half2 b1_ = __hadd2(__hadd2(u2h(pu[4]), u2h(pu[5])),
                                  __hadd2(u2h(pu[6]), u2h(pu[7])));
            float2 f1 = __half22float2(__hadd2(b0_, b1_));
            lac1 += f1.x + f1.y;
        }

        // ---- O += P @ V (V via ldmatrix.trans; P already fp16 A-frags) ----
#pragma unroll
        for (int ks = 0; ks < 4; ks++) {
            uint32_t a[4] = {pl[2 * ks], pu[2 * ks], pl[2 * ks + 1], pu[2 * ks + 1]};
            uint32_t bf[4][4];
#pragma unroll
            for (int np = 0; np < 4; np++)
                ldsm4t(bf[np], vbase + swz(ks * 16 + lg * 8 + l8, np * 2 + lhi));
#pragma unroll
            for (int ni = 0; ni < 8; ni++)
                mma_f16(oacc[ni], a, &bf[ni >> 1][(ni & 1) * 2]);
        }
    }

    // ---- epilogue: one-time row-sum reduce, normalize, fp16 store ----
    lac0 += __shfl_xor_sync(0xffffffffu, lac0, 1);
    lac0 += __shfl_xor_sync(0xffffffffu, lac0, 2);
    lac1 += __shfl_xor_sync(0xffffffffu, lac1, 1);
    lac1 += __shfl_xor_sync(0xffffffffu, lac1, 2);
    const float inv0 = 1.0f / lac0, inv1 = 1.0f / lac1;
    __half* Op0 = Og + ((size_t)b * SEQ + (m0 + wrow + lq)) * EMB + h * HD;
    __half* Op1 = Op0 + (size_t)8 * EMB;
#pragma unroll
    for (int ni = 0; ni < 8; ni++) {
        int c = ni * 8 + (lr << 1);
        *(__half2*)(Op0 + c) = __floats2half2_rn(oacc[ni][0] * inv0, oacc[ni][1] * inv0);
        *(__half2*)(Op1 + c) = __floats2half2_rn(oacc[ni][2] * inv1, oacc[ni][3] * inv1);
    }
}

// ---------------- launcher ---------------------------------------------------
extern "C" void kernel_launch(void* const* d_in, const int* in_sizes, int n_in,
                              void* d_out, int out_size)
{
    const float* hidden = (const float*)d_in[0];
    const float* attn_b = (const float*)d_in[1];
    const float* Wq = (const float*)d_in[2];
    const float* bq = (const float*)d_in[3];
    const float* Wk = (const float*)d_in[4];
    const float* bk = (const float*)d_in[5];
    const float* Wv = (const float*)d_in[6];
    const float* bv = (const float*)d_in[7];
    const float* Wo = (const float*)d_in[8];
    const float* bo = (const float*)d_in[9];
    float* out = (float*)d_out;

    __half *h16, *w16, *q16, *k16, *v16, *a16;
    cudaGetSymbolAddress((void**)&h16, g_h16);
    cudaGetSymbolAddress((void**)&w16, g_w16);
    cudaGetSymbolAddress((void**)&q16, g_q16);
    cudaGetSymbolAddress((void**)&k16, g_k16);
    cudaGetSymbolAddress((void**)&v16, g_v16);
    cudaGetSymbolAddress((void**)&a16, g_a16);

    const int GEMM_SMEM = 147456;               // 3 x (16KB A + 32KB W)
    const int FLASH_SMEM = 65536 + 3 * 34816;   // 169984
    cudaFuncSetAttribute(hgemm<true>, cudaFuncAttributeMaxDynamicSharedMemorySize, GEMM_SMEM);
    cudaFuncSetAttribute(hgemm<false>, cudaFuncAttributeMaxDynamicSharedMemorySize, GEMM_SMEM);
    cudaFuncSetAttribute(flash16, cudaFuncAttributeMaxDynamicSharedMemorySize, FLASH_SMEM);

    // fused f32 -> fp16 conversions (single launch)
    conv_all<<<8192, 256>>>((const float4*)hidden, (const float4*)Wq,
                            (const float4*)Wk, (const float4*)Wv, (const float4*)Wo,
                            (uint2*)h16, (uint2*)w16);

    // QKV projections (fp16 out; q pre-scaled by SCALING*LOG2E for exp2 softmax)
    hgemm<true><<<dim3(EMB / 256, (BSZ * SEQ) / 128, 3), 256, GEMM_SMEM>>>(
        h16, w16, w16 + 1048576, w16 + 2 * 1048576,
        bq, bk, bv, q16, k16, v16, SCALING * LOG2E);

    // fused attention (round-14 config)
    flash16<<<dim3(SEQ / 128, BSZ * NH), 256, FLASH_SMEM>>>(q16, k16, v16, attn_b, a16);

    // output projection (f32 out)
    hgemm<false><<<dim3(EMB / 256, (BSZ * SEQ) / 128, 1), 256, GEMM_SMEM>>>(
        a16, w16 + 3 * 1048576, w16 + 3 * 1048576, w16 + 3 * 1048576,
        bo, bo, bo, out, out, out, 1.0f);
}